// round 4
// baseline (speedup 1.0000x reference)
#include <cuda_runtime.h>

// ImprovedVectorizationLoss: fused masked-L1 + BCE + continuity + recon-MSE.
// Single kernel; per-block partials -> global atomics; last block (ticket)
// does cross-segment continuity fixup + final scalar + self-reset.

#define M_ROW 4096
#define TPB   256
#define SEGS  8
#define SEG   (M_ROW / SEGS)         // 512
#define TILE  256
#define NTILE (SEG / TILE)           // 2
#define RECON_BLOCKS 1024
#define BMAX  512
#define EPSV  1e-7f

__device__ float        g_acc[6];                  // [coord,width,bce,nvalid,cont,recon]
__device__ unsigned int g_ticket;
__device__ int          g_first_idx[BMAX * SEGS];
__device__ float2       g_first_p45[BMAX * SEGS];
__device__ float2       g_last_p45[BMAX * SEGS];

__device__ __forceinline__ float warpReduceSumF(float v) {
#pragma unroll
    for (int o = 16; o > 0; o >>= 1) v += __shfl_down_sync(0xffffffffu, v, o);
    return v;
}

__global__ __launch_bounds__(TPB) void loss_fused_kernel(
    const float* __restrict__ preds, const float* __restrict__ tgts,
    const float* __restrict__ rec,   const float* __restrict__ img,
    float* __restrict__ out, int B, int nrec, int nblocks)
{
    __shared__ float  sp[NTILE][TILE * 9];   // 18 KB
    __shared__ float  st[NTILE][TILE * 9];   // 18 KB
    __shared__ float2 s45[SEG];              // 4 KB
    __shared__ unsigned char smk[SEG];
    __shared__ int    schunk[TPB];
    __shared__ float  swred[6][8];
    __shared__ bool   s_is_last;

    const int tid  = threadIdx.x;
    const int bid  = blockIdx.x;
    const int lane = tid & 31;
    const int wid  = tid >> 5;
    const int nseg_blocks = B * SEGS;

    float coordS = 0.f, widthS = 0.f, bceS = 0.f, nvS = 0.f, contS = 0.f, reconS = 0.f;

    if (bid < nseg_blocks) {
        const int row = bid / SEGS;
        const int seg = bid - row * SEGS;
        const size_t segbase = ((size_t)row * M_ROW + (size_t)seg * SEG) * 9;

        // ---- stage BOTH tiles up front: 18 independent LDG.128 per thread ----
        {
            const float4* p4 = reinterpret_cast<const float4*>(preds + segbase);
            const float4* t4 = reinterpret_cast<const float4*>(tgts  + segbase);
            float4* sp4 = reinterpret_cast<float4*>(&sp[0][0]);
            float4* st4 = reinterpret_cast<float4*>(&st[0][0]);
            const int NF4 = NTILE * TILE * 9 / 4;   // 1152
#pragma unroll
            for (int i = tid; i < NF4; i += TPB) {
                sp4[i] = p4[i];
                st4[i] = t4[i];
            }
        }
        __syncthreads();

        // ---- one record per thread per tile, branch-free ----
#pragma unroll
        for (int tile = 0; tile < NTILE; tile++) {
            const float* pr = &sp[tile][tid * 9];
            const float* tr = &st[tile][tid * 9];
            float t8   = tr[8];
            float mask = (t8 > 0.5f) ? 1.0f : 0.0f;

            coordS += (fabsf(pr[0] - tr[0]) + fabsf(pr[1] - tr[1]) + fabsf(pr[2] - tr[2])
                     + fabsf(pr[3] - tr[3]) + fabsf(pr[4] - tr[4]) + fabsf(pr[5] - tr[5])) * mask;
            widthS += (fabsf(pr[6] - tr[6]) + fabsf(pr[7] - tr[7])) * mask;

            float p = fminf(fmaxf(pr[8], EPSV), 1.0f - EPSV);
            bceS   += -(t8 * __logf(p) + (1.0f - t8) * __logf(1.0f - p));
            nvS    += mask;

            int jseg = tile * TILE + tid;
            s45[jseg] = make_float2(pr[4], pr[5]);
            smk[jseg] = (unsigned char)(t8 > 0.5f ? 1 : 0);
        }
        __syncthreads();

        // ---- segment-local continuity via suffix-min over 512 entries ----
        {
            int j0 = 2 * tid, j1 = 2 * tid + 1;
            int p0 = smk[j0] ? j0 : SEG;
            int p1 = smk[j1] ? j1 : SEG;
            schunk[tid] = min(p0, p1);
        }
        __syncthreads();
#pragma unroll
        for (int off = 1; off < TPB; off <<= 1) {
            int v = schunk[tid];
            if (tid + off < TPB) v = min(v, schunk[tid + off]);
            __syncthreads();
            schunk[tid] = v;
            __syncthreads();
        }
        {
            const int rs = bid;   // == row*SEGS + seg
            int running = (tid < TPB - 1) ? schunk[tid + 1] : SEG;
#pragma unroll
            for (int jj = 1; jj >= 0; jj--) {
                int j = 2 * tid + jj;
                if (smk[j]) {
                    if (running < SEG) {
                        float2 a = s45[j], b = s45[running];
                        contS += 0.5f * (fabsf(a.x - b.x) + fabsf(a.y - b.y));
                    } else {
                        g_last_p45[rs] = s45[j];
                    }
                    running = j;
                }
            }
            if (tid == 0) {
                int f = schunk[0];
                g_first_idx[rs] = f;
                if (f < SEG) g_first_p45[rs] = s45[f];
            }
        }
    } else {
        const int rb = bid - nseg_blocks;
        const float4* r4 = reinterpret_cast<const float4*>(rec);
        const float4* i4 = reinterpret_cast<const float4*>(img);
        const int n4 = nrec >> 2;
        for (int i = rb * TPB + tid; i < n4; i += RECON_BLOCKS * TPB) {
            float4 r = r4[i], m = i4[i];
            float dx = r.x - m.x, dy = r.y - m.y, dz = r.z - m.z, dw = r.w - m.w;
            reconS += dx * dx + dy * dy + dz * dz + dw * dw;
        }
    }

    // ---- block reduce + global atomic accumulate ----
    float vals[6] = {coordS, widthS, bceS, nvS, contS, reconS};
#pragma unroll
    for (int q = 0; q < 6; q++) {
        float v = warpReduceSumF(vals[q]);
        if (lane == 0) swred[q][wid] = v;
    }
    __syncthreads();
    if (wid == 0 && lane < 6) {
        float v = 0.f;
#pragma unroll
        for (int j = 0; j < 8; j++) v += swred[lane][j];
        atomicAdd(&g_acc[lane], v);
    }
    __syncthreads();   // all writes of this block done before the release fence

    // ---- last-block finalize (release fence + ticket from ONE thread only) ----
    if (tid == 0) {
        __threadfence();   // cumulative release: publishes the whole block's writes
        unsigned int t = atomicAdd(&g_ticket, 1u);
        s_is_last = (t == (unsigned int)(nblocks - 1));
    }
    __syncthreads();
    if (!s_is_last) return;
    __threadfence();   // acquire (single block only — cheap)

    // cross-segment continuity fixup: one row per thread, prefetched loads
    float fix = 0.f;
    for (int r = tid; r < B; r += TPB) {
        int    fidx[SEGS];
        float2 fp[SEGS], lp[SEGS];
#pragma unroll
        for (int s = 0; s < SEGS; s++) {
            int rs = r * SEGS + s;
            fidx[s] = g_first_idx[rs];
            fp[s]   = g_first_p45[rs];
            lp[s]   = g_last_p45[rs];
        }
        float2 nf = make_float2(0.f, 0.f);
        bool have = false;
#pragma unroll
        for (int s = SEGS - 1; s >= 0; s--) {
            if (fidx[s] < SEG) {
                if (have) fix += 0.5f * (fabsf(lp[s].x - nf.x) + fabsf(lp[s].y - nf.y));
                nf = fp[s];
                have = true;
            }
        }
    }
    {
        float v = warpReduceSumF(fix);
        if (lane == 0) swred[0][wid] = v;
    }
    __syncthreads();
    if (tid == 0) {
        float fsum = 0.f;
#pragma unroll
        for (int j = 0; j < 8; j++) fsum += swred[0][j];

        double t0 = (double)g_acc[0], t1 = (double)g_acc[1], t2 = (double)g_acc[2];
        double nv = (double)g_acc[3];
        double t4 = (double)g_acc[4] + (double)fsum;
        double t5 = (double)g_acc[5];

        double coord    = (nv > 0.0) ? t0 / fmax(nv * 6.0, 1.0) : 0.0;
        double width    = (nv > 0.0) ? t1 / fmax(nv * 2.0, 1.0) : 0.0;
        double validity = t2 / ((double)B * (double)M_ROW);
        double cont     = t4 / (double)B;
        double recon    = t5 / (double)nrec;
        out[0] = (float)(coord + width + 2.0 * validity + 0.2 * cont + 0.1 * recon);

        // self-reset for the next graph replay
        g_ticket = 0u;
#pragma unroll
        for (int q = 0; q < 6; q++) g_acc[q] = 0.f;
        __threadfence();
    }
}

extern "C" void kernel_launch(void* const* d_in, const int* in_sizes, int n_in,
                              void* d_out, int out_size)
{
    const float* preds = (const float*)d_in[0];
    const float* tgts  = (const float*)d_in[1];
    const float* rec   = (const float*)d_in[2];
    const float* img   = (const float*)d_in[3];

    const int B    = in_sizes[0] / (M_ROW * 9);
    const int nrec = in_sizes[2];
    const int nblocks = B * SEGS + RECON_BLOCKS;

    loss_fused_kernel<<<nblocks, TPB>>>(preds, tgts, rec, img,
                                        (float*)d_out, B, nrec, nblocks);
}

// round 5
// speedup vs baseline: 1.1490x; 1.1490x over previous
#include <cuda_runtime.h>
#include <cstdint>

// ImprovedVectorizationLoss: fused masked-L1 + BCE + continuity + recon-MSE.
// Single kernel; cp.async double-buffered record staging; ballot-based
// continuity; global atomics + last-block (ticket) finalize & self-reset.

#define M_ROW 4096
#define TPB   256
#define SEGS  8
#define SEG   (M_ROW / SEGS)         // 512
#define TILE  256
#define NTILE (SEG / TILE)           // 2
#define NF4T  (TILE * 9 / 4)         // 576 float4 per tile per tensor
#define RECON_BLOCKS 1024
#define BMAX  512
#define EPSV  1e-7f

__device__ float        g_acc[6];                  // [coord,width,bce,nvalid,cont,recon]
__device__ unsigned int g_ticket;
__device__ int          g_first_idx[BMAX * SEGS];
__device__ float2       g_first_p45[BMAX * SEGS];
__device__ float2       g_last_p45[BMAX * SEGS];

__device__ __forceinline__ float warpReduceSumF(float v) {
#pragma unroll
    for (int o = 16; o > 0; o >>= 1) v += __shfl_down_sync(0xffffffffu, v, o);
    return v;
}

__device__ __forceinline__ void cp16(void* s, const void* g) {
    unsigned saddr = (unsigned)__cvta_generic_to_shared(s);
    asm volatile("cp.async.cg.shared.global [%0], [%1], 16;" :: "r"(saddr), "l"(g));
}
#define CP_COMMIT() asm volatile("cp.async.commit_group;")
#define CP_WAIT(n)  asm volatile("cp.async.wait_group %0;" :: "n"(n))

// Spread bits of x to even bit positions of a 64-bit word.
__device__ __forceinline__ uint64_t bitspread(uint32_t a) {
    uint64_t x = a;
    x = (x | (x << 16)) & 0x0000FFFF0000FFFFull;
    x = (x | (x << 8))  & 0x00FF00FF00FF00FFull;
    x = (x | (x << 4))  & 0x0F0F0F0F0F0F0F0Full;
    x = (x | (x << 2))  & 0x3333333333333333ull;
    x = (x | (x << 1))  & 0x5555555555555555ull;
    return x;
}

__global__ __launch_bounds__(TPB) void loss_fused_kernel(
    const float* __restrict__ preds, const float* __restrict__ tgts,
    const float* __restrict__ rec,   const float* __restrict__ img,
    float* __restrict__ out, int B, int nrec, int nblocks)
{
    __shared__ float  sp[NTILE][TILE * 9];   // 18 KB
    __shared__ float  st[NTILE][TILE * 9];   // 18 KB
    __shared__ float2 s45[SEG];              // 4 KB
    __shared__ unsigned char smk[SEG];
    __shared__ int    sfv[8];                // per-warp first-valid (global-in-seg idx)
    __shared__ float  swred[6][8];
    __shared__ bool   s_is_last;

    const int tid  = threadIdx.x;
    const int bid  = blockIdx.x;
    const int lane = tid & 31;
    const int wid  = tid >> 5;
    const int nseg_blocks = B * SEGS;

    float coordS = 0.f, widthS = 0.f, bceS = 0.f, nvS = 0.f, contS = 0.f, reconS = 0.f;

    if (bid < nseg_blocks) {
        const int row = bid / SEGS;
        const int seg = bid - row * SEGS;
        const size_t segbase = ((size_t)row * M_ROW + (size_t)seg * SEG) * 9;
        const float4* p4 = reinterpret_cast<const float4*>(preds + segbase);
        const float4* t4 = reinterpret_cast<const float4*>(tgts  + segbase);

        // ---- stage tile0 then tile1 via cp.async, separate commit groups ----
#pragma unroll
        for (int tl = 0; tl < NTILE; tl++) {
            float4* spd = reinterpret_cast<float4*>(&sp[tl][0]);
            float4* std_ = reinterpret_cast<float4*>(&st[tl][0]);
            for (int i = tid; i < NF4T; i += TPB) {
                cp16(&spd[i], &p4[tl * NF4T + i]);
                cp16(&std_[i], &t4[tl * NF4T + i]);
            }
            CP_COMMIT();
        }

        // ---- process tiles; tile1 copy overlaps tile0 compute ----
#pragma unroll
        for (int tile = 0; tile < NTILE; tile++) {
            if (tile == 0) CP_WAIT(1); else CP_WAIT(0);
            __syncthreads();

            const float* pr = &sp[tile][tid * 9];
            const float* tr = &st[tile][tid * 9];
            float t8   = tr[8];
            float mask = (t8 > 0.5f) ? 1.0f : 0.0f;

            coordS += (fabsf(pr[0] - tr[0]) + fabsf(pr[1] - tr[1]) + fabsf(pr[2] - tr[2])
                     + fabsf(pr[3] - tr[3]) + fabsf(pr[4] - tr[4]) + fabsf(pr[5] - tr[5])) * mask;
            widthS += (fabsf(pr[6] - tr[6]) + fabsf(pr[7] - tr[7])) * mask;

            float p = fminf(fmaxf(pr[8], EPSV), 1.0f - EPSV);
            bceS   += -(t8 * __logf(p) + (1.0f - t8) * __logf(1.0f - p));
            nvS    += mask;

            int jseg = tile * TILE + tid;
            s45[jseg] = make_float2(pr[4], pr[5]);
            smk[jseg] = (unsigned char)(t8 > 0.5f ? 1 : 0);
        }
        __syncthreads();

        // ---- continuity: ballot masks, ffs next-valid ----
        // Warp w owns entries [64w, 64w+64); thread lane l owns 64w+2l, 64w+2l+1.
        const int base = wid * 64;
        unsigned v0 = smk[base + 2 * lane];
        unsigned v1 = smk[base + 2 * lane + 1];
        unsigned b0 = __ballot_sync(0xffffffffu, v0 != 0);
        unsigned b1 = __ballot_sync(0xffffffffu, v1 != 0);
        uint64_t m64 = bitspread(b0) | (bitspread(b1) << 1);

        {
            int fvloc = m64 ? (__ffsll((long long)m64) - 1) : 64;
            if (lane == 0) sfv[wid] = (fvloc < 64) ? (base + fvloc) : SEG;
        }
        __syncthreads();

        int nxt_cross = SEG;
#pragma unroll
        for (int w2 = 7; w2 >= 0; w2--) {
            if (w2 > wid) nxt_cross = min(nxt_cross, sfv[w2]);
        }

        const int rs = bid;   // == row*SEGS + seg
#pragma unroll
        for (int jj = 0; jj < 2; jj++) {
            int pbit = 2 * lane + jj;
            unsigned valid = (jj == 0) ? v0 : v1;
            if (valid) {
                int j = base + pbit;
                int nxt;
                if (pbit < 63) {
                    uint64_t rem = m64 & (~0ull << (pbit + 1));
                    nxt = rem ? (base + __ffsll((long long)rem) - 1) : nxt_cross;
                } else {
                    nxt = nxt_cross;
                }
                if (nxt < SEG) {
                    float2 a = s45[j], b = s45[nxt];
                    contS += 0.5f * (fabsf(a.x - b.x) + fabsf(a.y - b.y));
                } else {
                    g_last_p45[rs] = s45[j];   // unique last valid in segment
                }
            }
        }
        if (tid == 0) {
            int f = SEG;
#pragma unroll
            for (int w2 = 0; w2 < 8; w2++) f = min(f, sfv[w2]);
            g_first_idx[rs] = f;
            if (f < SEG) g_first_p45[rs] = s45[f];
        }
    } else {
        const int rb = bid - nseg_blocks;
        const float4* r4 = reinterpret_cast<const float4*>(rec);
        const float4* i4 = reinterpret_cast<const float4*>(img);
        const int n4 = nrec >> 2;
        for (int i = rb * TPB + tid; i < n4; i += RECON_BLOCKS * TPB) {
            float4 r = r4[i], m = i4[i];
            float dx = r.x - m.x, dy = r.y - m.y, dz = r.z - m.z, dw = r.w - m.w;
            reconS += dx * dx + dy * dy + dz * dz + dw * dw;
        }
    }

    // ---- block reduce + global atomic accumulate ----
    float vals[6] = {coordS, widthS, bceS, nvS, contS, reconS};
#pragma unroll
    for (int q = 0; q < 6; q++) {
        float v = warpReduceSumF(vals[q]);
        if (lane == 0) swred[q][wid] = v;
    }
    __syncthreads();
    if (wid == 0 && lane < 6) {
        float v = 0.f;
#pragma unroll
        for (int j = 0; j < 8; j++) v += swred[lane][j];
        atomicAdd(&g_acc[lane], v);
    }
    __syncthreads();

    // ---- last-block finalize ----
    if (tid == 0) {
        __threadfence();   // release: publishes this block's writes (cumulative)
        unsigned int t = atomicAdd(&g_ticket, 1u);
        s_is_last = (t == (unsigned int)(nblocks - 1));
    }
    __syncthreads();
    if (!s_is_last) return;
    __threadfence();       // acquire (single block)

    float fix = 0.f;
    for (int r = tid; r < B; r += TPB) {
        int    fidx[SEGS];
        float2 fp[SEGS], lp[SEGS];
#pragma unroll
        for (int s = 0; s < SEGS; s++) {
            int q = r * SEGS + s;
            fidx[s] = g_first_idx[q];
            fp[s]   = g_first_p45[q];
            lp[s]   = g_last_p45[q];
        }
        float2 nf = make_float2(0.f, 0.f);
        bool have = false;
#pragma unroll
        for (int s = SEGS - 1; s >= 0; s--) {
            if (fidx[s] < SEG) {
                if (have) fix += 0.5f * (fabsf(lp[s].x - nf.x) + fabsf(lp[s].y - nf.y));
                nf = fp[s];
                have = true;
            }
        }
    }
    {
        float v = warpReduceSumF(fix);
        if (lane == 0) swred[0][wid] = v;
    }
    __syncthreads();
    if (tid == 0) {
        float fsum = 0.f;
#pragma unroll
        for (int j = 0; j < 8; j++) fsum += swred[0][j];

        double t0 = (double)g_acc[0], t1 = (double)g_acc[1], t2 = (double)g_acc[2];
        double nv = (double)g_acc[3];
        double t4 = (double)g_acc[4] + (double)fsum;
        double t5 = (double)g_acc[5];

        double coord    = (nv > 0.0) ? t0 / fmax(nv * 6.0, 1.0) : 0.0;
        double width    = (nv > 0.0) ? t1 / fmax(nv * 2.0, 1.0) : 0.0;
        double validity = t2 / ((double)B * (double)M_ROW);
        double cont     = t4 / (double)B;
        double recon    = t5 / (double)nrec;
        out[0] = (float)(coord + width + 2.0 * validity + 0.2 * cont + 0.1 * recon);

        g_ticket = 0u;
#pragma unroll
        for (int q = 0; q < 6; q++) g_acc[q] = 0.f;
        __threadfence();
    }
}

extern "C" void kernel_launch(void* const* d_in, const int* in_sizes, int n_in,
                              void* d_out, int out_size)
{
    const float* preds = (const float*)d_in[0];
    const float* tgts  = (const float*)d_in[1];
    const float* rec   = (const float*)d_in[2];
    const float* img   = (const float*)d_in[3];

    const int B    = in_sizes[0] / (M_ROW * 9);
    const int nrec = in_sizes[2];
    const int nblocks = B * SEGS + RECON_BLOCKS;

    loss_fused_kernel<<<nblocks, TPB>>>(preds, tgts, rec, img,
                                        (float*)d_out, B, nrec, nblocks);
}